// round 9
// baseline (speedup 1.0000x reference)
#include <cuda_runtime.h>
#include <cstdint>
#include <math.h>

// N=8 blocks, D=2048, B*L=8192 rows. Cluster-2 split-D: each CTA handles a
// 1024-col half-row (TMA-staged, 32KB smem), partners exchange 16 partial
// sums via DSMEM + cluster-scope mbarrier. 4 CTAs/SM, ~2.7us phase units.
#define NB 8
#define DDIM 2048
#define HALF_D 1024
#define THREADS 256
#define SLICE_BYTES (HALF_D * 4)            // 4 KB per block half-slice
#define SMEM_BYTES (NB * HALF_D * 4)        // 32 KB data stage

__device__ __forceinline__ void mbar_wait_cta(unsigned int mb) {
    unsigned int done;
    asm volatile(
        "{\n\t.reg .pred p;\n\t"
        "mbarrier.try_wait.parity.acquire.cta.shared::cta.b64 p, [%1], 0;\n\t"
        "selp.b32 %0, 1, 0, p;\n\t}"
        : "=r"(done) : "r"(mb) : "memory");
    if (!done) {
        asm volatile(
            "{\n\t.reg .pred P1;\n\t"
            "WL_%=:\n\t"
            "mbarrier.try_wait.parity.acquire.cta.shared::cta.b64 P1, [%0], 0, 0x989680;\n\t"
            "@P1 bra.uni WD_%=;\n\t"
            "bra.uni WL_%=;\n\t"
            "WD_%=:\n\t}"
            :: "r"(mb) : "memory");
    }
}

__device__ __forceinline__ void mbar_wait_cluster(unsigned int mb) {
    unsigned int done;
    asm volatile(
        "{\n\t.reg .pred p;\n\t"
        "mbarrier.try_wait.parity.acquire.cluster.shared::cta.b64 p, [%1], 0;\n\t"
        "selp.b32 %0, 1, 0, p;\n\t}"
        : "=r"(done) : "r"(mb) : "memory");
    if (!done) {
        asm volatile(
            "{\n\t.reg .pred P1;\n\t"
            "WL_%=:\n\t"
            "mbarrier.try_wait.parity.acquire.cluster.shared::cta.b64 P1, [%0], 0, 0x989680;\n\t"
            "@P1 bra.uni WD_%=;\n\t"
            "bra.uni WL_%=;\n\t"
            "WD_%=:\n\t}"
            :: "r"(mb) : "memory");
    }
}

__global__ __launch_bounds__(THREADS, 4) __cluster_dims__(2, 1, 1)
void attn_residual_kernel(const float* __restrict__ blocks,     // [7, BL, D]
                          const float* __restrict__ partial,    // [BL, D]
                          const float* __restrict__ norm_scale, // [D]
                          const float* __restrict__ proj,       // [D]
                          float* __restrict__ out,              // [BL, D]
                          int BL)
{
    extern __shared__ float sv[];          // [NB][HALF_D]
    __shared__ __align__(8) unsigned long long tbar[2];  // TMA phase barriers
    __shared__ __align__(8) unsigned long long pbar;     // partner barrier
    __shared__ float peer_vals[16];
    __shared__ float red[THREADS / 32][16];
    __shared__ float fin[16];

    const int t    = threadIdx.x;
    const int lane = t & 31;
    const int warp = t >> 5;

    unsigned int rank;
    asm("mov.u32 %0, %%cluster_ctarank;" : "=r"(rank));

    const int row  = blockIdx.x >> 1;     // cluster id
    const int half = blockIdx.x & 1;      // == rank

    const size_t nStride = (size_t)BL * DDIM;
    const size_t baseOff = (size_t)row * DDIM + (size_t)half * HALF_D;

    const int lt = t * 4;                  // local col within half [0,1024)

    unsigned int svb, tb0, tb1, pb, pvb;
    asm("{ .reg .u64 a; cvta.to.shared.u64 a, %1; cvt.u32.u64 %0, a; }"
        : "=r"(svb) : "l"(sv));
    asm("{ .reg .u64 a; cvta.to.shared.u64 a, %1; cvt.u32.u64 %0, a; }"
        : "=r"(tb0) : "l"(&tbar[0]));
    tb1 = tb0 + 8;
    asm("{ .reg .u64 a; cvta.to.shared.u64 a, %1; cvt.u32.u64 %0, a; }"
        : "=r"(pb) : "l"(&pbar));
    asm("{ .reg .u64 a; cvta.to.shared.u64 a, %1; cvt.u32.u64 %0, a; }"
        : "=r"(pvb) : "l"(peer_vals));

    // ---- Init barriers ----
    if (t == 0) {
        asm volatile("mbarrier.init.shared.b64 [%0], 1;"  :: "r"(tb0) : "memory");
        asm volatile("mbarrier.init.shared.b64 [%0], 1;"  :: "r"(tb1) : "memory");
        asm volatile("mbarrier.init.shared.b64 [%0], 16;" :: "r"(pb)  : "memory");
    }
    __syncthreads();

    // ---- Issue TMA bulk copies for my 8 half-slices (4KB each) ----
    if (t == 0) {
        asm volatile("mbarrier.arrive.expect_tx.shared.b64 _, [%0], %1;"
                     :: "r"(tb0), "r"(4 * SLICE_BYTES) : "memory");
        asm volatile("mbarrier.arrive.expect_tx.shared.b64 _, [%0], %1;"
                     :: "r"(tb1), "r"(4 * SLICE_BYTES) : "memory");
#pragma unroll
        for (int n = 0; n < NB; n++) {
            const float* src = (n < NB - 1)
                                 ? (blocks + (size_t)n * nStride + baseOff)
                                 : (partial + baseOff);
            const unsigned mb = (n < 4) ? tb0 : tb1;
            asm volatile(
                "cp.async.bulk.shared::cluster.global.mbarrier::complete_tx::bytes"
                " [%0], [%1], %2, [%3];"
                :: "r"(svb + (unsigned)(n * SLICE_BYTES)), "l"(src),
                   "r"(SLICE_BYTES), "r"(mb)
                : "memory");
        }
    }

    // ---- Cluster barrier: both CTAs' pbar init visible before any peer
    //      arrival. Cost hidden under the in-flight TMA copies. ----
    asm volatile("barrier.cluster.arrive.aligned;" ::: "memory");
    asm volatile("barrier.cluster.wait.aligned;" ::: "memory");

    // q[d] = proj[d] * norm_scale[d] for my 4 columns
    float4 q;
    {
        float4 p = *(const float4*)(proj + half * HALF_D + lt);
        float4 s = *(const float4*)(norm_scale + half * HALF_D + lt);
        q = make_float4(p.x * s.x, p.y * s.y, p.z * s.z, p.w * s.w);
    }

    float dotp[NB], ssq[NB];
#define PROC(n)                                                              \
    do {                                                                     \
        float4 a = *(const float4*)(sv + (n) * HALF_D + lt);                 \
        dotp[n] = q.x * a.x + q.y * a.y + q.z * a.z + q.w * a.w;             \
        ssq[n]  = a.x * a.x + a.y * a.y + a.z * a.z + a.w * a.w;             \
    } while (0)

    mbar_wait_cta(tb0);
    PROC(0); PROC(1); PROC(2); PROC(3);
#pragma unroll
    for (int n = 0; n < 4; n++) {
#pragma unroll
        for (int o = 16; o > 0; o >>= 1) {
            dotp[n] += __shfl_down_sync(0xffffffffu, dotp[n], o);
            ssq[n]  += __shfl_down_sync(0xffffffffu, ssq[n],  o);
        }
    }
    mbar_wait_cta(tb1);
    PROC(4); PROC(5); PROC(6); PROC(7);
#undef PROC
#pragma unroll
    for (int n = 4; n < NB; n++) {
#pragma unroll
        for (int o = 16; o > 0; o >>= 1) {
            dotp[n] += __shfl_down_sync(0xffffffffu, dotp[n], o);
            ssq[n]  += __shfl_down_sync(0xffffffffu, ssq[n],  o);
        }
    }

    // ---- Cross-warp combine -> 16 half-row partials ----
    if (lane == 0) {
#pragma unroll
        for (int n = 0; n < NB; n++) {
            red[warp][n]     = dotp[n];
            red[warp][8 + n] = ssq[n];
        }
    }
    __syncthreads();
    if (t < 16) {
        float s = 0.f;
#pragma unroll
        for (int w = 0; w < THREADS / 32; w++) s += red[w][t];
        fin[t] = s;
        // Send my partial to the partner CTA's peer_vals[t], then arrive
        // (release, cluster scope) on the partner's pbar.
        unsigned int rAddr, rBar;
        const unsigned int prank = rank ^ 1u;
        asm volatile("mapa.shared::cluster.u32 %0, %1, %2;"
                     : "=r"(rAddr) : "r"(pvb + (unsigned)t * 4u), "r"(prank));
        asm volatile("mapa.shared::cluster.u32 %0, %1, %2;"
                     : "=r"(rBar) : "r"(pb), "r"(prank));
        asm volatile("st.shared::cluster.b32 [%0], %1;"
                     :: "r"(rAddr), "f"(s) : "memory");
        asm volatile("mbarrier.arrive.release.cluster.shared::cluster.b64 _, [%0];"
                     :: "r"(rBar) : "memory");
    }
    __syncthreads();                 // order fin[] writes for all threads
    mbar_wait_cluster(pb);           // partner's 16 partials have landed

    // ---- Softmax over n from full-row sums (redundant per-thread) ----
    float wgt[NB];
    float mx = -INFINITY;
#pragma unroll
    for (int n = 0; n < NB; n++) {
        float d = fin[n] + peer_vals[n];
        float s = fin[8 + n] + peer_vals[8 + n];
        float rms = sqrtf(s * (1.0f / DDIM) + 1e-6f);
        wgt[n] = d / rms;
        mx = fmaxf(mx, wgt[n]);
    }
    float wsum = 0.f;
#pragma unroll
    for (int n = 0; n < NB; n++) {
        wgt[n] = __expf(wgt[n] - mx);
        wsum += wgt[n];
    }
    const float inv = 1.0f / wsum;

    // ---- Pass 2: weighted sum over my half; streaming store ----
    float4 o = make_float4(0.f, 0.f, 0.f, 0.f);
#pragma unroll
    for (int n = 0; n < NB; n++) {
        float w = wgt[n] * inv;
        float4 a = *(const float4*)(sv + n * HALF_D + lt);
        o.x += w * a.x; o.y += w * a.y; o.z += w * a.z; o.w += w * a.w;
    }
    __stcs((float4*)(out + baseOff + lt), o);

    // No trailing cluster sync needed beyond correctness: partner reads only
    // peer_vals (written before its wait); my smem stays valid until exit,
    // and the cluster retires together.
    asm volatile("barrier.cluster.arrive.aligned;" ::: "memory");
    asm volatile("barrier.cluster.wait.aligned;" ::: "memory");
}

extern "C" void kernel_launch(void* const* d_in, const int* in_sizes, int n_in,
                              void* d_out, int out_size)
{
    const float* blocks     = (const float*)d_in[0];
    const float* partial    = (const float*)d_in[1];
    const float* norm_scale = (const float*)d_in[2];
    const float* proj       = (const float*)d_in[3];
    float* out              = (float*)d_out;

    const int BL = in_sizes[1] / DDIM;

    static int configured = 0;
    if (!configured) {
        cudaFuncSetAttribute(attn_residual_kernel,
                             cudaFuncAttributeMaxDynamicSharedMemorySize,
                             SMEM_BYTES);
        configured = 1;
    }

    attn_residual_kernel<<<2 * BL, THREADS, SMEM_BYTES>>>(blocks, partial,
                                                          norm_scale, proj,
                                                          out, BL);
}

// round 10
// speedup vs baseline: 1.7101x; 1.7101x over previous
#include <cuda_runtime.h>
#include <cstdint>
#include <math.h>

// N=8 (7 completed blocks + partial), D=2048, B*L=8192 rows.
// R8 structure (grid=BL, 3 CTAs/SM, TMA bulk stage-in) with FOUR mbarrier
// phases (2 slices each): compute starts after 16KB lands and each pair's
// shuffle reduction overlaps the next pair's arrivals.
#define NB 8
#define DDIM 2048
#define THREADS 256
#define ROW_BYTES (DDIM * 4)              // 8 KB per block slice
#define SMEM_BYTES (NB * DDIM * 4)        // 64 KB data stage
#define NPHASE 4

__device__ __forceinline__ void mbar_wait(unsigned int mb) {
    unsigned int done;
    asm volatile(
        "{\n\t"
        ".reg .pred p;\n\t"
        "mbarrier.try_wait.parity.acquire.cta.shared::cta.b64 p, [%1], 0;\n\t"
        "selp.b32 %0, 1, 0, p;\n\t"
        "}" : "=r"(done) : "r"(mb) : "memory");
    if (!done) {
        asm volatile(
            "{\n\t"
            ".reg .pred P1;\n\t"
            "WAIT_LOOP_%=:\n\t"
            "mbarrier.try_wait.parity.acquire.cta.shared::cta.b64 P1, [%0], 0, 0x989680;\n\t"
            "@P1 bra.uni WAIT_DONE_%=;\n\t"
            "bra.uni WAIT_LOOP_%=;\n\t"
            "WAIT_DONE_%=:\n\t"
            "}" :: "r"(mb) : "memory");
    }
}

__global__ __launch_bounds__(THREADS, 3)
void attn_residual_kernel(const float* __restrict__ blocks,     // [7, BL, D]
                          const float* __restrict__ partial,    // [BL, D]
                          const float* __restrict__ norm_scale, // [D]
                          const float* __restrict__ proj,       // [D]
                          float* __restrict__ out,              // [BL, D]
                          int BL)
{
    extern __shared__ float sv[];         // [NB][DDIM], 16B aligned
    __shared__ __align__(8) unsigned long long mbar[NPHASE];
    __shared__ float red[THREADS / 32][16];
    __shared__ float fin[16];

    const int row  = blockIdx.x;
    const int t    = threadIdx.x;
    const int lane = t & 31;
    const int warp = t >> 5;

    const size_t rowOff  = (size_t)row * DDIM;
    const size_t nStride = (size_t)BL * DDIM;

    const int d0 = t * 4;            // [0, 1024)
    const int d1 = 1024 + t * 4;     // [1024, 2048)

    unsigned int svb, mbb;
    asm("{ .reg .u64 tmp; cvta.to.shared.u64 tmp, %1; cvt.u32.u64 %0, tmp; }"
        : "=r"(svb) : "l"(sv));
    asm("{ .reg .u64 tmp; cvta.to.shared.u64 tmp, %1; cvt.u32.u64 %0, tmp; }"
        : "=r"(mbb) : "l"(&mbar[0]));

    // ---- Init mbarriers, then bulk-copy 8 contiguous 8KB slices ----
    if (t == 0) {
#pragma unroll
        for (int p = 0; p < NPHASE; p++)
            asm volatile("mbarrier.init.shared.b64 [%0], 1;"
                         :: "r"(mbb + 8u * p) : "memory");
    }
    __syncthreads();

    if (t == 0) {
#pragma unroll
        for (int p = 0; p < NPHASE; p++)
            asm volatile("mbarrier.arrive.expect_tx.shared.b64 _, [%0], %1;"
                         :: "r"(mbb + 8u * p), "r"(2 * ROW_BYTES) : "memory");
#pragma unroll
        for (int n = 0; n < NB; n++) {
            const float* src = (n < NB - 1)
                                 ? (blocks + (size_t)n * nStride + rowOff)
                                 : (partial + rowOff);
            asm volatile(
                "cp.async.bulk.shared::cluster.global.mbarrier::complete_tx::bytes"
                " [%0], [%1], %2, [%3];"
                :: "r"(svb + (unsigned)(n * ROW_BYTES)), "l"(src),
                   "r"(ROW_BYTES), "r"(mbb + 8u * (n >> 1))
                : "memory");
        }
    }

    // q[d] = proj[d] * norm_scale[d] (overlaps with bulk copies)
    float4 q0, q1;
    {
        float4 p = *(const float4*)(proj + d0);
        float4 s = *(const float4*)(norm_scale + d0);
        q0 = make_float4(p.x * s.x, p.y * s.y, p.z * s.z, p.w * s.w);
        p = *(const float4*)(proj + d1);
        s = *(const float4*)(norm_scale + d1);
        q1 = make_float4(p.x * s.x, p.y * s.y, p.z * s.z, p.w * s.w);
    }

    float dotp[NB], ssq[NB];

#define PROC(n)                                                              \
    do {                                                                     \
        float4 a = *(const float4*)(sv + (n) * DDIM + d0);                   \
        float4 b = *(const float4*)(sv + (n) * DDIM + d1);                   \
        dotp[n] = q0.x * a.x + q0.y * a.y + q0.z * a.z + q0.w * a.w          \
                + q1.x * b.x + q1.y * b.y + q1.z * b.z + q1.w * b.w;         \
        ssq[n]  = a.x * a.x + a.y * a.y + a.z * a.z + a.w * a.w              \
                + b.x * b.x + b.y * b.y + b.z * b.z + b.w * b.w;             \
    } while (0)

#define REDUCE_PAIR(n0)                                                      \
    do {                                                                     \
        _Pragma("unroll")                                                    \
        for (int n = (n0); n < (n0) + 2; n++) {                              \
            _Pragma("unroll")                                                \
            for (int o = 16; o > 0; o >>= 1) {                               \
                dotp[n] += __shfl_down_sync(0xffffffffu, dotp[n], o);        \
                ssq[n]  += __shfl_down_sync(0xffffffffu, ssq[n],  o);        \
            }                                                                \
        }                                                                    \
    } while (0)

    // ---- 4 phases: wait 16KB, compute pair, reduce pair (overlaps next) ----
    mbar_wait(mbb + 0);  PROC(0); PROC(1); REDUCE_PAIR(0);
    mbar_wait(mbb + 8);  PROC(2); PROC(3); REDUCE_PAIR(2);
    mbar_wait(mbb + 16); PROC(4); PROC(5); REDUCE_PAIR(4);
    mbar_wait(mbb + 24); PROC(6); PROC(7); REDUCE_PAIR(6);
#undef PROC
#undef REDUCE_PAIR

    // ---- Cross-warp reduction of 16 scalars ----
    if (lane == 0) {
#pragma unroll
        for (int n = 0; n < NB; n++) {
            red[warp][n]     = dotp[n];
            red[warp][8 + n] = ssq[n];
        }
    }
    __syncthreads();
    if (t < 16) {
        float s = 0.f;
#pragma unroll
        for (int w = 0; w < THREADS / 32; w++) s += red[w][t];
        fin[t] = s;
    }
    __syncthreads();

    // ---- Softmax over n (redundant per-thread; trivial) ----
    float wgt[NB];
    float mx = -INFINITY;
#pragma unroll
    for (int n = 0; n < NB; n++) {
        float rms = sqrtf(fin[8 + n] * (1.0f / DDIM) + 1e-6f);
        wgt[n] = fin[n] / rms;
        mx = fmaxf(mx, wgt[n]);
    }
    float wsum = 0.f;
#pragma unroll
    for (int n = 0; n < NB; n++) {
        wgt[n] = __expf(wgt[n] - mx);
        wsum += wgt[n];
    }
    const float inv = 1.0f / wsum;

    // ---- Pass 2: weighted sum from smem; streaming store ----
    float4 o0 = make_float4(0.f, 0.f, 0.f, 0.f);
    float4 o1 = make_float4(0.f, 0.f, 0.f, 0.f);
#pragma unroll
    for (int n = 0; n < NB; n++) {
        float w = wgt[n] * inv;
        float4 a = *(const float4*)(sv + n * DDIM + d0);
        float4 b = *(const float4*)(sv + n * DDIM + d1);
        o0.x += w * a.x; o0.y += w * a.y; o0.z += w * a.z; o0.w += w * a.w;
        o1.x += w * b.x; o1.y += w * b.y; o1.z += w * b.z; o1.w += w * b.w;
    }
    __stcs((float4*)(out + rowOff + d0), o0);
    __stcs((float4*)(out + rowOff + d1), o1);
}

extern "C" void kernel_launch(void* const* d_in, const int* in_sizes, int n_in,
                              void* d_out, int out_size)
{
    const float* blocks     = (const float*)d_in[0];
    const float* partial    = (const float*)d_in[1];
    const float* norm_scale = (const float*)d_in[2];
    const float* proj       = (const float*)d_in[3];
    float* out              = (float*)d_out;

    const int BL = in_sizes[1] / DDIM;

    static int configured = 0;
    if (!configured) {
        cudaFuncSetAttribute(attn_residual_kernel,
                             cudaFuncAttributeMaxDynamicSharedMemorySize,
                             SMEM_BYTES);
        configured = 1;
    }

    attn_residual_kernel<<<BL, THREADS, SMEM_BYTES>>>(blocks, partial,
                                                      norm_scale, proj,
                                                      out, BL);
}